// round 1
// baseline (speedup 1.0000x reference)
#include <cuda_runtime.h>

#define B 64
#define C 1501
#define D 2048
#define D4 (D / 4)          // 512 float4 per row
#define TOT4 (C * D4)       // 768512 float4 per [C,D] tile
#define ALPHA 0.01f
#define EPS 1e-7f

__device__ int g_owner[C];
__device__ int g_cls[B];

// Resolve cls dtype (int32 vs int64) and compute last-write-wins owner per row.
__global__ void prep_kernel(const int* __restrict__ cls_raw) {
    int tid = threadIdx.x;
    __shared__ int s_is64;
    if (tid == 0) {
        // int64 little-endian: words 1,3,...,63 are high halves of cls[0..31],
        // all zero since 0 <= cls < 1501. int32: they are random class ids.
        int any = 0;
#pragma unroll
        for (int i = 1; i < B; i += 2) any |= cls_raw[i];
        s_is64 = (any == 0) ? 1 : 0;
    }
    for (int c = tid; c < C; c += blockDim.x) g_owner[c] = -1;
    __syncthreads();
    if (tid < B) {
        int cls = s_is64 ? cls_raw[2 * tid] : cls_raw[tid];
        g_cls[tid] = cls;
        atomicMax(&g_owner[cls], tid);  // last write wins -> max b
    }
}

// selected[b] = ORIGINAL memory[cls[b]] (gather happens before scatter)
__global__ void selected_kernel(const float4* __restrict__ mem4,
                                float4* __restrict__ sel4) {
    int b = blockIdx.x;
    int cls = g_cls[b];
    const float4* src = mem4 + (size_t)cls * D4;
    float4* dst = sel4 + (size_t)b * D4;
    for (int d = threadIdx.x; d < D4; d += blockDim.x) dst[d] = src[d];
}

// tmp_repeated[b,c,d] = tmp_memory[c,d] for all b. One load (L2-resident
// source), 64 coalesced streaming stores. HBM-write bound.
__global__ void repeat_kernel(const float4* __restrict__ x4,
                              const float4* __restrict__ mem4,
                              float4* __restrict__ out4) {
    int g = blockIdx.x * blockDim.x + threadIdx.x;
    if (g >= TOT4) return;
    int c = g / D4;
    int d = g - c * D4;
    int ow = g_owner[c];
    float4 v = (ow >= 0) ? x4[(size_t)ow * D4 + d] : mem4[g];
#pragma unroll 8
    for (int b = 0; b < B; b++) {
        out4[(size_t)b * TOT4 + g] = v;
    }
}

// new_mem[c] = normalize(memory[c]*(1-a) + tmp_memory[c]*a)
__global__ void newmem_kernel(const float4* __restrict__ x4,
                              const float4* __restrict__ mem4,
                              float4* __restrict__ out4) {
    int c = blockIdx.x;
    int ow = g_owner[c];
    int t = threadIdx.x;  // 256 threads, 2 float4 each
    float4 y[2];
    float ss = 0.f;
#pragma unroll
    for (int i = 0; i < 2; i++) {
        int d = t + i * 256;
        float4 m = mem4[(size_t)c * D4 + d];
        float4 tv = (ow >= 0) ? x4[(size_t)ow * D4 + d] : m;
        float4 yy;
        yy.x = m.x * (1.f - ALPHA) + tv.x * ALPHA;
        yy.y = m.y * (1.f - ALPHA) + tv.y * ALPHA;
        yy.z = m.z * (1.f - ALPHA) + tv.z * ALPHA;
        yy.w = m.w * (1.f - ALPHA) + tv.w * ALPHA;
        ss += yy.x * yy.x + yy.y * yy.y + yy.z * yy.z + yy.w * yy.w;
        y[i] = yy;
    }
    // block reduce ss (256 threads = 8 warps)
    __shared__ float s_red[8];
#pragma unroll
    for (int off = 16; off > 0; off >>= 1)
        ss += __shfl_xor_sync(0xffffffffu, ss, off);
    if ((t & 31) == 0) s_red[t >> 5] = ss;
    __syncthreads();
    if (t < 32) {
        float v = (t < 8) ? s_red[t] : 0.f;
#pragma unroll
        for (int off = 4; off > 0; off >>= 1)
            v += __shfl_xor_sync(0xffffffffu, v, off);
        if (t == 0) s_red[0] = v;
    }
    __syncthreads();
    float inv = 1.f / (sqrtf(s_red[0]) + EPS);
#pragma unroll
    for (int i = 0; i < 2; i++) {
        int d = t + i * 256;
        float4 yy = y[i];
        yy.x *= inv; yy.y *= inv; yy.z *= inv; yy.w *= inv;
        out4[(size_t)c * D4 + d] = yy;
    }
}

extern "C" void kernel_launch(void* const* d_in, const int* in_sizes, int n_in,
                              void* d_out, int out_size) {
    const float* x = (const float*)d_in[0];
    const int* cls = (const int*)d_in[1];
    const float* memory = (const float*)d_in[2];
    float* out = (float*)d_out;

    float* sel = out;                              // [B, D]
    float* tmp = out + (size_t)B * D;              // [B, C, D]
    float* nm = tmp + (size_t)B * C * D;           // [C, D]

    const float4* x4 = (const float4*)x;
    const float4* mem4 = (const float4*)memory;

    prep_kernel<<<1, 256>>>(cls);
    selected_kernel<<<B, 256>>>(mem4, (float4*)sel);
    repeat_kernel<<<(TOT4 + 255) / 256, 256>>>(x4, mem4, (float4*)tmp);
    newmem_kernel<<<C, 256>>>(x4, mem4, (float4*)nm);
}

// round 2
// speedup vs baseline: 1.1158x; 1.1158x over previous
#include <cuda_runtime.h>

#define B 64
#define C 1501
#define D 2048
#define D4 (D / 4)          // 512 float4 per row
#define TOT4 (C * D4)       // 768512 float4 per [C,D] tile
#define ALPHA 0.01f
#define EPS 1e-7f

// Fully fused: one block per memory row c (512 threads, one float4 each).
//  - loads cls (dtype-detected int32/int64) into smem
//  - scans for last-write-wins owner of row c; writes selected[b] for all b
//    with cls[b]==c (original memory row, read-before-scatter semantics)
//  - streams tmp_memory[c] to all 64 repeat destinations (evict-first stores)
//  - computes EMA + row L2-normalize and writes new_mem[c]
__global__ __launch_bounds__(512) void fused_kernel(
    const float4* __restrict__ x4,
    const float4* __restrict__ mem4,
    const int* __restrict__ cls_raw,
    float4* __restrict__ sel4,
    float4* __restrict__ rep4,
    float4* __restrict__ nm4) {
    const int c = blockIdx.x;
    const int t = threadIdx.x;  // 0..511

    __shared__ int s_cls[B];
    __shared__ int s_is64;
    __shared__ float s_red[16];

    if (t == 0) {
        // int64 little-endian: odd words within the first 64 are high halves
        // of cls[0..31], all zero since 0 <= cls < 1501. int32: random ids.
        int any = 0;
#pragma unroll
        for (int i = 1; i < B; i += 2) any |= cls_raw[i];
        s_is64 = (any == 0) ? 1 : 0;
    }
    __syncthreads();
    if (t < B) s_cls[t] = s_is64 ? cls_raw[2 * t] : cls_raw[t];
    __syncthreads();

    const size_t row_off = (size_t)c * D4 + t;
    const float4 m = __ldg(mem4 + row_off);

    // Owner scan + selected gather (m is the ORIGINAL memory row).
    int ow = -1;
#pragma unroll
    for (int b = 0; b < B; b++) {
        if (s_cls[b] == c) {
            ow = b;                       // max b wins (last write wins)
            sel4[(size_t)b * D4 + t] = m; // selected[b] = memory[cls[b]]
        }
    }

    const float4 v = (ow >= 0) ? __ldg(x4 + (size_t)ow * D4 + t) : m;

    // 787 MB streaming writes: tmp_repeated[b, c, :] = v for all b.
#pragma unroll 8
    for (int b = 0; b < B; b++) {
        __stcs(rep4 + (size_t)b * TOT4 + row_off, v);
    }

    // EMA + L2 normalize for new_mem[c].
    float4 y;
    y.x = m.x * (1.f - ALPHA) + v.x * ALPHA;
    y.y = m.y * (1.f - ALPHA) + v.y * ALPHA;
    y.z = m.z * (1.f - ALPHA) + v.z * ALPHA;
    y.w = m.w * (1.f - ALPHA) + v.w * ALPHA;
    float ss = y.x * y.x + y.y * y.y + y.z * y.z + y.w * y.w;

#pragma unroll
    for (int off = 16; off > 0; off >>= 1)
        ss += __shfl_xor_sync(0xffffffffu, ss, off);
    if ((t & 31) == 0) s_red[t >> 5] = ss;
    __syncthreads();
    if (t < 32) {
        float u = (t < 16) ? s_red[t] : 0.f;
#pragma unroll
        for (int off = 8; off > 0; off >>= 1)
            u += __shfl_xor_sync(0xffffffffu, u, off);
        if (t == 0) s_red[0] = u;
    }
    __syncthreads();

    const float inv = 1.f / (sqrtf(s_red[0]) + EPS);
    y.x *= inv; y.y *= inv; y.z *= inv; y.w *= inv;
    nm4[row_off] = y;
}

extern "C" void kernel_launch(void* const* d_in, const int* in_sizes, int n_in,
                              void* d_out, int out_size) {
    const float* x = (const float*)d_in[0];
    const int* cls = (const int*)d_in[1];
    const float* memory = (const float*)d_in[2];
    float* out = (float*)d_out;

    float* sel = out;                    // [B, D]
    float* rep = out + (size_t)B * D;    // [B, C, D]
    float* nm = rep + (size_t)B * C * D; // [C, D]

    fused_kernel<<<C, 512>>>((const float4*)x, (const float4*)memory, cls,
                             (float4*)sel, (float4*)rep, (float4*)nm);
}